// round 9
// baseline (speedup 1.0000x reference)
#include <cuda_runtime.h>
#include <cuda_bf16.h>
#include <cstdint>

// Problem constants
#define BB 4
#define TT 2048
#define CC 768
#define HH 12
#define DD 64
#define NQ (BB * HH * TT * DD)

// Pre-split bf16 hi/lo intermediates (producer writes split once)
__device__ __nv_bfloat16 g_qh[NQ], g_ql[NQ];
__device__ __nv_bfloat16 g_kh[NQ], g_kl[NQ];
__device__ __nv_bfloat16 g_vh[NQ], g_vl[NQ];
__device__ __nv_bfloat16 g_oh[BB * TT * CC], g_ol[BB * TT * CC];

static __device__ __forceinline__ uint32_t smem_u32(const void* p) {
    uint32_t a;
    asm("{ .reg .u64 t; cvta.to.shared.u64 t, %1; cvt.u32.u64 %0, t; }"
        : "=r"(a) : "l"(p));
    return a;
}

static __device__ __forceinline__ void ldm4(uint32_t* r, uint32_t addr) {
    asm volatile("ldmatrix.sync.aligned.m8n8.x4.shared.b16 {%0,%1,%2,%3}, [%4];"
                 : "=r"(r[0]), "=r"(r[1]), "=r"(r[2]), "=r"(r[3]) : "r"(addr));
}
static __device__ __forceinline__ void ldm4t(uint32_t* r, uint32_t addr) {
    asm volatile("ldmatrix.sync.aligned.m8n8.x4.trans.shared.b16 {%0,%1,%2,%3}, [%4];"
                 : "=r"(r[0]), "=r"(r[1]), "=r"(r[2]), "=r"(r[3]) : "r"(addr));
}

static __device__ __forceinline__ void mma16816(float* d, const uint32_t* a,
                                                const uint32_t* b) {
    asm volatile(
        "mma.sync.aligned.m16n8k16.row.col.f32.bf16.bf16.f32 "
        "{%0,%1,%2,%3}, {%4,%5,%6,%7}, {%8,%9}, {%0,%1,%2,%3};"
        : "+f"(d[0]), "+f"(d[1]), "+f"(d[2]), "+f"(d[3])
        : "r"(a[0]), "r"(a[1]), "r"(a[2]), "r"(a[3]), "r"(b[0]), "r"(b[1]));
}

static __device__ __forceinline__ void split2(float f0, float f1,
                                              uint32_t& hi, uint32_t& lo) {
    __nv_bfloat16 h0 = __float2bfloat16(f0);
    __nv_bfloat16 h1 = __float2bfloat16(f1);
    __nv_bfloat16 l0 = __float2bfloat16(f0 - __bfloat162float(h0));
    __nv_bfloat16 l1 = __float2bfloat16(f1 - __bfloat162float(h1));
    __nv_bfloat162 hh = __halves2bfloat162(h0, h1);
    __nv_bfloat162 ll = __halves2bfloat162(l0, l1);
    hi = *reinterpret_cast<uint32_t*>(&hh);
    lo = *reinterpret_cast<uint32_t*>(&ll);
}

// FMA-pipe exp2 (no MUFU). Valid for x <= 0; clamps at -126.
static __device__ __forceinline__ float exp2f_fast(float x) {
    x = fmaxf(x, -126.0f);
    float z = x + 12582912.0f;
    int i = __float_as_int(z) - 0x4B400000;
    float f = x - (z - 12582912.0f);
    float p = 0.00133336f;
    p = fmaf(p, f, 0.00961813f);
    p = fmaf(p, f, 0.05550411f);
    p = fmaf(p, f, 0.24022651f);
    p = fmaf(p, f, 0.69314718f);
    p = fmaf(p, f, 1.0f);
    return p * __int_as_float((i + 127) << 23);
}
#define L2E 1.4426950408889634f

#define STS4(addr, a, b, c, d) \
    asm volatile("st.shared.v4.b32 [%0], {%1,%2,%3,%4};" :: \
                 "r"(addr), "r"(a), "r"(b), "r"(c), "r"(d) : "memory")

// ===========================================================================
// Split-bf16 HMMA GEMM, warp tile 64x64.
// CTA tile 256(M) x 128(N), K-chunk 16, 48B-padded smem rows, reg prefetch.
// Smem: A_hi[256][48] | A_lo | B_hi[128][48] | B_lo  = 36864B.
// 8 warps = 4(M) x 2(N); per warp 4 mt x 8 nt m16n8k16 tiles.
// EPI 0: A=x fp32 (split on load), RoPE epilogue -> g_{q,k,v}{h,l}
// EPI 1: A=pre-split g_oh/g_ol (copy), plain fp32 store
// ===========================================================================
#define GST 48
#define A_TILE 12288       // 256*48
#define B_TILE 6144        // 128*48
#define NCHUNK 48          // 768/16

template <int EPI>
__global__ __launch_bounds__(256) void gemm_mma_kernel(
    const float* __restrict__ Am, const float* __restrict__ Bm,
    const float* __restrict__ rsin, const float* __restrict__ rcos,
    float* __restrict__ outp)
{
    __shared__ __align__(16) char smem[2 * A_TILE + 2 * B_TILE];
    const uint32_t sb = smem_u32(smem);
    const uint32_t sA_hi = sb, sA_lo = sb + A_TILE;
    const uint32_t sB_hi = sb + 2 * A_TILE, sB_lo = sB_hi + B_TILE;

    const int tid = threadIdx.x;
    const int lane = tid & 31, warp = tid >> 5;
    const int warpM = warp & 3, warpN = warp >> 2;      // 4 x 2
    const int mBase = blockIdx.y * 256, nBase = blockIdx.x * 128;

    // loader: every thread owns A row tid; threads >=128 also own B row tid-128
    const bool hasB = tid >= 128;
    const int bRow = tid & 127;
    const size_t aOffG = (size_t)(mBase + tid) * 768;
    const size_t bOffG = (size_t)(nBase + bRow) * 768;
    const uint32_t dAhi = sA_hi + (uint32_t)tid * GST;
    const uint32_t dAlo = dAhi + A_TILE;
    const uint32_t dBhi = sB_hi + (uint32_t)bRow * GST;
    const uint32_t dBlo = dBhi + B_TILE;

    uint4 pfA[4], pfB[4];

    auto prefetch = [&](int c) {
        if (EPI == 1) {
            const uint4* ph = (const uint4*)(g_oh + aOffG + c * 16);
            const uint4* pl = (const uint4*)(g_ol + aOffG + c * 16);
            pfA[0] = ph[0]; pfA[1] = ph[1];
            pfA[2] = pl[0]; pfA[3] = pl[1];
        } else {
            const uint4* p = (const uint4*)(Am + aOffG + c * 16);
            pfA[0] = p[0]; pfA[1] = p[1]; pfA[2] = p[2]; pfA[3] = p[3];
        }
        if (hasB) {
            const uint4* p = (const uint4*)(Bm + bOffG + c * 16);
            pfB[0] = p[0]; pfB[1] = p[1]; pfB[2] = p[2]; pfB[3] = p[3];
        }
    };
    auto stschunk = [&]() {
        if (EPI == 1) {
            STS4(dAhi, pfA[0].x, pfA[0].y, pfA[0].z, pfA[0].w);
            STS4(dAhi + 16, pfA[1].x, pfA[1].y, pfA[1].z, pfA[1].w);
            STS4(dAlo, pfA[2].x, pfA[2].y, pfA[2].z, pfA[2].w);
            STS4(dAlo + 16, pfA[3].x, pfA[3].y, pfA[3].z, pfA[3].w);
        } else {
            const float* f = (const float*)pfA;
            uint32_t h[8], l[8];
#pragma unroll
            for (int q = 0; q < 8; q++) split2(f[2 * q], f[2 * q + 1], h[q], l[q]);
            STS4(dAhi, h[0], h[1], h[2], h[3]);
            STS4(dAhi + 16, h[4], h[5], h[6], h[7]);
            STS4(dAlo, l[0], l[1], l[2], l[3]);
            STS4(dAlo + 16, l[4], l[5], l[6], l[7]);
        }
        if (hasB) {
            const float* f = (const float*)pfB;
            uint32_t h[8], l[8];
#pragma unroll
            for (int q = 0; q < 8; q++) split2(f[2 * q], f[2 * q + 1], h[q], l[q]);
            STS4(dBhi, h[0], h[1], h[2], h[3]);
            STS4(dBhi + 16, h[4], h[5], h[6], h[7]);
            STS4(dBlo, l[0], l[1], l[2], l[3]);
            STS4(dBlo + 16, l[4], l[5], l[6], l[7]);
        }
    };

    const uint32_t aoff = sA_hi +
        (uint32_t)(warpM * 64 + (lane & 7) + ((lane >> 3) & 1) * 8) * GST +
        ((lane >> 4) & 1) * 16;
    const uint32_t boff = sB_hi +
        (uint32_t)(warpN * 64 + (lane & 7) + ((lane >> 4) & 1) * 8) * GST +
        ((lane >> 3) & 1) * 16;

    float acc[4][8][4];
#pragma unroll
    for (int mt = 0; mt < 4; mt++)
#pragma unroll
        for (int nt = 0; nt < 8; nt++)
#pragma unroll
            for (int r = 0; r < 4; r++) acc[mt][nt][r] = 0.0f;

    prefetch(0);
    for (int c = 0; c < NCHUNK; c++) {
        stschunk();
        __syncthreads();
        if (c + 1 < NCHUNK) prefetch(c + 1);   // LDG overlaps compute below

        uint32_t bh[4][4], bl[4][4];
#pragma unroll
        for (int p = 0; p < 4; p++) {
            ldm4(bh[p], boff + p * (16 * GST));
            ldm4(bl[p], boff + B_TILE + p * (16 * GST));
        }
#pragma unroll
        for (int mt = 0; mt < 4; mt++) {
            uint32_t ah[4], al[4];
            ldm4(ah, aoff + mt * (16 * GST));
            ldm4(al, aoff + A_TILE + mt * (16 * GST));
#pragma unroll
            for (int nt = 0; nt < 8; nt++) {
                const uint32_t* bhf = &bh[nt >> 1][(nt & 1) * 2];
                const uint32_t* blf = &bl[nt >> 1][(nt & 1) * 2];
                mma16816(acc[mt][nt], ah, bhf);
                mma16816(acc[mt][nt], ah, blf);
                mma16816(acc[mt][nt], al, bhf);
            }
        }
        __syncthreads();
    }

    const int gRow = lane >> 2;
    const int gCol = (lane & 3) * 2;
#pragma unroll
    for (int mt = 0; mt < 4; mt++) {
#pragma unroll
        for (int half = 0; half < 2; half++) {
            const int row_g = mBase + warpM * 64 + mt * 16 + gRow + half * 8;
#pragma unroll
            for (int nt = 0; nt < 8; nt++) {
                const float v1 = acc[mt][nt][half * 2];
                const float v2 = acc[mt][nt][half * 2 + 1];
                const int col_g = nBase + warpN * 64 + nt * 8 + gCol;
                if (EPI == 0) {
                    const int b = row_g >> 11, t = row_g & 2047;
                    const int s_idx = nBase / 768;
                    const int rem = col_g - s_idx * 768;
                    const int h = rem >> 6, d = rem & 63;
                    const size_t off = ((size_t)(b * HH + h) * TT + t) * DD + d;
                    uint32_t hi, lo;
                    if (s_idx < 2) {
                        const float sc = (s_idx == 0) ? 0.125f : 1.0f;
                        const float sn = rsin[t * 32 + (d >> 1)];
                        const float cs = rcos[t * 32 + (d >> 1)];
                        split2((v1 * cs - v2 * sn) * sc,
                               (v1 * sn + v2 * cs) * sc, hi, lo);
                        __nv_bfloat16* dh = (s_idx == 0) ? g_qh : g_kh;
                        __nv_bfloat16* dl = (s_idx == 0) ? g_ql : g_kl;
                        *(uint32_t*)(dh + off) = hi;
                        *(uint32_t*)(dl + off) = lo;
                    } else {
                        split2(v1, v2, hi, lo);
                        *(uint32_t*)(g_vh + off) = hi;
                        *(uint32_t*)(g_vl + off) = lo;
                    }
                } else {
                    *(float2*)(outp + (size_t)row_g * 768 + col_g) =
                        make_float2(v1, v2);
                }
            }
        }
    }
}

// ===========================================================================
// Flash attention, split-bf16 HMMA, pre-split operands (unchanged, round-8).
// ===========================================================================
#define KST 144

__global__ __launch_bounds__(256) void attn_mma_kernel()
{
    __shared__ __align__(16) char smem[36864];
    const uint32_t sb = smem_u32(smem);
    const uint32_t sKhi = sb, sKlo = sb + 9216;
    const uint32_t sVhi = sb + 18432, sVlo = sb + 27648;

    const int tid = threadIdx.x, lane = tid & 31, warp = tid >> 5;
    const int qi = gridDim.x - 1 - blockIdx.x;
    const int bh = blockIdx.y;
    const size_t bhOff = (size_t)bh * TT * DD;
    const int qBase = qi * 128;

    {
        const int row = tid >> 1, half = tid & 1;
        const uint4* ph = (const uint4*)(g_qh + bhOff + (size_t)(qBase + row) * 64 + half * 32);
        const uint4* pl = (const uint4*)(g_ql + bhOff + (size_t)(qBase + row) * 64 + half * 32);
        const uint32_t dh = sb + (uint32_t)row * KST + half * 64;
#pragma unroll
        for (int g = 0; g < 4; g++) {
            uint4 h = ph[g], l = pl[g];
            STS4(dh + g * 16, h.x, h.y, h.z, h.w);
            STS4(dh + 18432 + g * 16, l.x, l.y, l.z, l.w);
        }
    }
    __syncthreads();

    uint32_t qh[4][4], ql[4][4];
    {
        const uint32_t aoff = sb +
            (uint32_t)(warp * 16 + (lane & 7) + ((lane >> 3) & 1) * 8) * KST +
            ((lane >> 4) & 1) * 16;
#pragma unroll
        for (int kh = 0; kh < 4; kh++) {
            ldm4(qh[kh], aoff + kh * 32);
            ldm4(ql[kh], aoff + 18432 + kh * 32);
        }
    }
    __syncthreads();

    float o[8][4];
#pragma unroll
    for (int dn = 0; dn < 8; dn++)
#pragma unroll
        for (int r = 0; r < 4; r++) o[dn][r] = 0.0f;
    float mrow[2] = {-1e30f, -1e30f};
    float lrow[2] = {0.0f, 0.0f};

    const uint32_t boff =
        (uint32_t)((lane & 7) + ((lane >> 4) & 1) * 8) * KST +
        ((lane >> 3) & 1) * 16;
    const uint32_t voff =
        (uint32_t)((lane & 7) + ((lane >> 3) & 1) * 8) * KST +
        ((lane >> 4) & 1) * 16;
    const int jtEnd = 2 * qi + 1;

    for (int jt = 0; jt <= jtEnd; jt++) {
        {
            const size_t src0 = bhOff + (size_t)jt * 64 * 64;
#pragma unroll
            for (int g = 0; g < 2; g++) {
                const int id = tid + g * 256;
                const int row = id >> 3, part = id & 7;
                const size_t s = src0 + (size_t)row * 64 + part * 8;
                const uint32_t d = (uint32_t)row * KST + part * 16;
                uint4 v;
                v = *(const uint4*)(g_kh + s); STS4(sKhi + d, v.x, v.y, v.z, v.w);
                v = *(const uint4*)(g_kl + s); STS4(sKlo + d, v.x, v.y, v.z, v.w);
                v = *(const uint4*)(g_vh + s); STS4(sVhi + d, v.x, v.y, v.z, v.w);
                v = *(const uint4*)(g_vl + s); STS4(sVlo + d, v.x, v.y, v.z, v.w);
            }
        }
        __syncthreads();

        float s[8][4];
#pragma unroll
        for (int nt = 0; nt < 8; nt++)
#pragma unroll
            for (int r = 0; r < 4; r++) s[nt][r] = 0.0f;
#pragma unroll
        for (int kh = 0; kh < 4; kh++) {
#pragma unroll
            for (int p = 0; p < 4; p++) {
                uint32_t kbh[4], kbl[4];
                ldm4(kbh, sKhi + boff + p * (16 * KST) + kh * 32);
                ldm4(kbl, sKlo + boff + p * (16 * KST) + kh * 32);
#pragma unroll
                for (int sub = 0; sub < 2; sub++) {
                    float* d = s[2 * p + sub];
                    mma16816(d, qh[kh], &kbh[sub * 2]);
                    mma16816(d, qh[kh], &kbl[sub * 2]);
                    mma16816(d, ql[kh], &kbh[sub * 2]);
                }
            }
        }

        if (jt >= 2 * qi) {
            const int row0 = qBase + warp * 16 + (lane >> 2);
            const int colb = jt * 64 + 2 * (lane & 3);
#pragma unroll
            for (int nt = 0; nt < 8; nt++) {
                const int c = colb + nt * 8;
#pragma unroll
                for (int r = 0; r < 4; r++) {
                    const int row = row0 + ((r >> 1) << 3);
                    const int col = c + (r & 1);
                    if (col > row) s[nt][r] = -1e30f;
                }
            }
        }

        float mx0 = -1e30f, mx1 = -1e30f;
#pragma unroll
        for (int nt = 0; nt < 8; nt++) {
            mx0 = fmaxf(mx0, fmaxf(s[nt][0], s[nt][1]));
            mx1 = fmaxf(mx1, fmaxf(s[nt][2], s[nt][3]));
        }
        mx0 = fmaxf(mx0, __shfl_xor_sync(0xffffffffu, mx0, 1));
        mx0 = fmaxf(mx0, __shfl_xor_sync(0xffffffffu, mx0, 2));
        mx1 = fmaxf(mx1, __shfl_xor_sync(0xffffffffu, mx1, 1));
        mx1 = fmaxf(mx1, __shfl_xor_sync(0xffffffffu, mx1, 2));
        const float mn0 = fmaxf(mrow[0], mx0);
        const float mn1 = fmaxf(mrow[1], mx1);
        const float a0 = exp2f_fast((mrow[0] - mn0) * L2E);
        const float a1 = exp2f_fast((mrow[1] - mn1) * L2E);
        mrow[0] = mn0; mrow[1] = mn1;
        float rs0 = 0.0f, rs1 = 0.0f;
#pragma unroll
        for (int nt = 0; nt < 8; nt++) {
            s[nt][0] = exp2f_fast((s[nt][0] - mn0) * L2E);
            s[nt][1] = exp2f_fast((s[nt][1] - mn0) * L2E);
            s[nt][2] = exp2f_fast((s[nt][2] - mn1) * L2E);
            s[nt][3] = exp2f_fast((s[nt][3] - mn1) * L2E);
            rs0 += s[nt][0] + s[nt][1];
            rs1 += s[nt][2] + s[nt][3];
        }
        rs0 += __shfl_xor_sync(0xffffffffu, rs0, 1);
        rs0 += __shfl_xor_sync(0xffffffffu, rs0, 2);
        rs1 += __shfl_xor_sync(0xffffffffu, rs1, 1);
        rs1 += __shfl_xor_sync(0xffffffffu, rs1, 2);
        lrow[0] = lrow[0] * a0 + rs0;
        lrow[1] = lrow[1] * a1 + rs1;
#pragma unroll
        for (int dn = 0; dn < 8; dn++) {
            o[dn][0] *= a0; o[dn][1] *= a0;
            o[dn][2] *= a1; o[dn][3] *= a1;
        }

#pragma unroll
        for (int kh = 0; kh < 4; kh++) {
            uint32_t ph[4], pl[4];
#pragma unroll
            for (int idx = 0; idx < 4; idx++) {
                const int nt = 2 * kh + (idx >> 1);
                const int rb = (idx & 1) * 2;
                split2(s[nt][rb], s[nt][rb + 1], ph[idx], pl[idx]);
            }
#pragma unroll
            for (int p = 0; p < 4; p++) {
                uint32_t vbh[4], vbl[4];
                ldm4t(vbh, sVhi + voff + kh * (16 * KST) + p * 32);
                ldm4t(vbl, sVlo + voff + kh * (16 * KST) + p * 32);
#pragma unroll
                for (int sub = 0; sub < 2; sub++) {
                    float* d = o[2 * p + sub];
                    mma16816(d, ph, &vbh[sub * 2]);
                    mma16816(d, ph, &vbl[sub * 2]);
                    mma16816(d, pl, &vbh[sub * 2]);
                }
            }
        }
        __syncthreads();
    }

    const int b = bh / HH, h = bh % HH;
    const float inv0 = 1.0f / lrow[0];
    const float inv1 = 1.0f / lrow[1];
    const int row0 = qBase + warp * 16 + (lane >> 2);
    const int colb = h * 64 + 2 * (lane & 3);
#pragma unroll
    for (int dn = 0; dn < 8; dn++) {
        const int col = colb + dn * 8;
        uint32_t hi, lo;
        split2(o[dn][0] * inv0, o[dn][1] * inv0, hi, lo);
        *(uint32_t*)(g_oh + (size_t)(b * TT + row0) * CC + col) = hi;
        *(uint32_t*)(g_ol + (size_t)(b * TT + row0) * CC + col) = lo;
        split2(o[dn][2] * inv1, o[dn][3] * inv1, hi, lo);
        *(uint32_t*)(g_oh + (size_t)(b * TT + row0 + 8) * CC + col) = hi;
        *(uint32_t*)(g_ol + (size_t)(b * TT + row0 + 8) * CC + col) = lo;
    }
}

// ---------------------------------------------------------------------------
extern "C" void kernel_launch(void* const* d_in, const int* in_sizes, int n_in,
                              void* d_out, int out_size)
{
    const float* x      = (const float*)d_in[0];
    const float* w_qkv  = (const float*)d_in[1];
    const float* w_proj = (const float*)d_in[2];
    const float* rsin   = (const float*)d_in[3];
    const float* rcos   = (const float*)d_in[4];
    float* out = (float*)d_out;

    // QKV: M=8192 (32 x 256), N=2304 (18 x 128)
    gemm_mma_kernel<0><<<dim3(18, 32), 256>>>(x, w_qkv, rsin, rcos, nullptr);
    // Attention: 16 q-tiles of 128 x 48 (b,h)
    attn_mma_kernel<<<dim3(16, 48), 256>>>();
    // Proj: M=8192, N=768 (6 x 128)
    gemm_mma_kernel<1><<<dim3(6, 32), 256>>>(nullptr, w_proj, rsin, rcos, out);
}

// round 10
// speedup vs baseline: 1.0802x; 1.0802x over previous
#include <cuda_runtime.h>
#include <cuda_bf16.h>
#include <cstdint>

// Problem constants
#define BB 4
#define TT 2048
#define CC 768
#define HH 12
#define DD 64
#define NQ (BB * HH * TT * DD)

// Pre-split bf16 hi/lo tensors
__device__ __nv_bfloat16 g_qh[NQ], g_ql[NQ];
__device__ __nv_bfloat16 g_kh[NQ], g_kl[NQ];
__device__ __nv_bfloat16 g_vh[NQ], g_vl[NQ];
__device__ __nv_bfloat16 g_oh[BB * TT * CC], g_ol[BB * TT * CC];
__device__ __nv_bfloat16 g_xh[BB * TT * CC], g_xl[BB * TT * CC];
__device__ __nv_bfloat16 g_wqh[3 * CC * CC], g_wql[3 * CC * CC];
__device__ __nv_bfloat16 g_wph[CC * CC], g_wpl[CC * CC];

static __device__ __forceinline__ uint32_t smem_u32(const void* p) {
    uint32_t a;
    asm("{ .reg .u64 t; cvta.to.shared.u64 t, %1; cvt.u32.u64 %0, t; }"
        : "=r"(a) : "l"(p));
    return a;
}

static __device__ __forceinline__ void ldm4(uint32_t* r, uint32_t addr) {
    asm volatile("ldmatrix.sync.aligned.m8n8.x4.shared.b16 {%0,%1,%2,%3}, [%4];"
                 : "=r"(r[0]), "=r"(r[1]), "=r"(r[2]), "=r"(r[3]) : "r"(addr));
}
static __device__ __forceinline__ void ldm4t(uint32_t* r, uint32_t addr) {
    asm volatile("ldmatrix.sync.aligned.m8n8.x4.trans.shared.b16 {%0,%1,%2,%3}, [%4];"
                 : "=r"(r[0]), "=r"(r[1]), "=r"(r[2]), "=r"(r[3]) : "r"(addr));
}

static __device__ __forceinline__ void mma16816(float* d, const uint32_t* a,
                                                const uint32_t* b) {
    asm volatile(
        "mma.sync.aligned.m16n8k16.row.col.f32.bf16.bf16.f32 "
        "{%0,%1,%2,%3}, {%4,%5,%6,%7}, {%8,%9}, {%0,%1,%2,%3};"
        : "+f"(d[0]), "+f"(d[1]), "+f"(d[2]), "+f"(d[3])
        : "r"(a[0]), "r"(a[1]), "r"(a[2]), "r"(a[3]), "r"(b[0]), "r"(b[1]));
}

static __device__ __forceinline__ void split2(float f0, float f1,
                                              uint32_t& hi, uint32_t& lo) {
    __nv_bfloat16 h0 = __float2bfloat16(f0);
    __nv_bfloat16 h1 = __float2bfloat16(f1);
    __nv_bfloat16 l0 = __float2bfloat16(f0 - __bfloat162float(h0));
    __nv_bfloat16 l1 = __float2bfloat16(f1 - __bfloat162float(h1));
    __nv_bfloat162 hh = __halves2bfloat162(h0, h1);
    __nv_bfloat162 ll = __halves2bfloat162(l0, l1);
    hi = *reinterpret_cast<uint32_t*>(&hh);
    lo = *reinterpret_cast<uint32_t*>(&ll);
}

// FMA-pipe exp2 (no MUFU). Valid for x <= 0; clamps at -126.
static __device__ __forceinline__ float exp2f_fast(float x) {
    x = fmaxf(x, -126.0f);
    float z = x + 12582912.0f;
    int i = __float_as_int(z) - 0x4B400000;
    float f = x - (z - 12582912.0f);
    float p = 0.00133336f;
    p = fmaf(p, f, 0.00961813f);
    p = fmaf(p, f, 0.05550411f);
    p = fmaf(p, f, 0.24022651f);
    p = fmaf(p, f, 0.69314718f);
    p = fmaf(p, f, 1.0f);
    return p * __int_as_float((i + 127) << 23);
}
#define L2E 1.4426950408889634f

#define STS4(addr, a, b, c, d) \
    asm volatile("st.shared.v4.b32 [%0], {%1,%2,%3,%4};" :: \
                 "r"(addr), "r"(a), "r"(b), "r"(c), "r"(d) : "memory")
#define CP16(dst, src) \
    asm volatile("cp.async.ca.shared.global [%0], [%1], 16;" :: \
                 "r"(dst), "l"(src) : "memory")
#define CP_COMMIT() asm volatile("cp.async.commit_group;" ::: "memory")
#define CP_WAIT1()  asm volatile("cp.async.wait_group 1;" ::: "memory")
#define CP_WAIT0()  asm volatile("cp.async.wait_group 0;" ::: "memory")

// ===========================================================================
// Split kernel: fp32 -> bf16 hi/lo (vectorized, grid-stride)
// ===========================================================================
__global__ void split_kernel(const float* __restrict__ src,
                             __nv_bfloat16* __restrict__ h,
                             __nv_bfloat16* __restrict__ l, int n4)
{
    for (int i = blockIdx.x * blockDim.x + threadIdx.x; i < n4;
         i += gridDim.x * blockDim.x) {
        float4 v = ((const float4*)src)[i];
        uint32_t h01, l01, h23, l23;
        split2(v.x, v.y, h01, l01);
        split2(v.z, v.w, h23, l23);
        ((uint2*)h)[i] = make_uint2(h01, h23);
        ((uint2*)l)[i] = make_uint2(l01, l23);
    }
}

// ===========================================================================
// GEMM v3: split-bf16 HMMA, cp.async 2-stage ping-pong.
// CTA 128(M) x 128(N), K-chunk 16. Smem = 2 stages x 24576B = 49152B.
//   stage: Ah[128][48] @0 | Al @6144 | Bh @12288 | Bl @18432
// 8 warps = 4(M) x 2(N); warp tile 32 x 64 (2 mt x 8 nt).
// Inputs pre-split bf16. EPI 0: RoPE scatter -> g_{q,k,v}{h,l}.
// EPI 1: plain fp32 store to outp.
// ===========================================================================
#define GST 48
#define STAGE_B 24576
#define NCHUNK 48

template <int EPI>
__global__ __launch_bounds__(256) void gemm_mma_kernel(
    const float* __restrict__ rsin, const float* __restrict__ rcos,
    float* __restrict__ outp)
{
    __shared__ __align__(16) char smem[2 * STAGE_B];
    const uint32_t sb = smem_u32(smem);

    const int tid = threadIdx.x;
    const int lane = tid & 31, warp = tid >> 5;
    const int warpM = warp & 3, warpN = warp >> 2;   // 4 x 2
    const int mBase = blockIdx.y * 128, nBase = blockIdx.x * 128;

    const __nv_bfloat16* Ah = (EPI == 0) ? g_xh : g_oh;
    const __nv_bfloat16* Al = (EPI == 0) ? g_xl : g_ol;
    const __nv_bfloat16* Bh = (EPI == 0) ? g_wqh : g_wph;
    const __nv_bfloat16* Bl = (EPI == 0) ? g_wql : g_wpl;

    // loader: thread t -> row t&127, buffer t>>7 (0=hi, 1=lo)
    const int lrow = tid & 127, sel = tid >> 7;
    const __nv_bfloat16* srcA = (sel ? Al : Ah) + (size_t)(mBase + lrow) * 768;
    const __nv_bfloat16* srcB = (sel ? Bl : Bh) + (size_t)(nBase + lrow) * 768;
    const uint32_t dA = sb + sel * 6144 + (uint32_t)lrow * GST;
    const uint32_t dB = sb + 12288 + sel * 6144 + (uint32_t)lrow * GST;

    const uint32_t aoff = sb +
        (uint32_t)(warpM * 32 + (lane & 7) + ((lane >> 3) & 1) * 8) * GST +
        ((lane >> 4) & 1) * 16;
    const uint32_t boff = sb + 12288 +
        (uint32_t)(warpN * 64 + (lane & 7) + ((lane >> 4) & 1) * 8) * GST +
        ((lane >> 3) & 1) * 16;

    float acc[2][8][4];
#pragma unroll
    for (int mt = 0; mt < 2; mt++)
#pragma unroll
        for (int nt = 0; nt < 8; nt++)
#pragma unroll
            for (int r = 0; r < 4; r++) acc[mt][nt][r] = 0.0f;

    // prologue: stage 0
    CP16(dA, srcA); CP16(dA + 16, srcA + 8);
    CP16(dB, srcB); CP16(dB + 16, srcB + 8);
    CP_COMMIT();

    for (int c = 0; c < NCHUNK; c++) {
        const uint32_t stOff = (uint32_t)(c & 1) * STAGE_B;
        if (c + 1 < NCHUNK) {
            const uint32_t ns = (uint32_t)((c + 1) & 1) * STAGE_B;
            const __nv_bfloat16* pa = srcA + (c + 1) * 16;
            const __nv_bfloat16* pb = srcB + (c + 1) * 16;
            CP16(dA + ns, pa); CP16(dA + ns + 16, pa + 8);
            CP16(dB + ns, pb); CP16(dB + ns + 16, pb + 8);
            CP_COMMIT();
            CP_WAIT1();          // stage c arrived
        } else {
            CP_WAIT0();
        }
        __syncthreads();

        uint32_t bh[4][4], bl[4][4];
#pragma unroll
        for (int p = 0; p < 4; p++) {
            ldm4(bh[p], boff + stOff + p * (16 * GST));
            ldm4(bl[p], boff + stOff + 6144 + p * (16 * GST));
        }
#pragma unroll
        for (int mt = 0; mt < 2; mt++) {
            uint32_t ah[4], al[4];
            ldm4(ah, aoff + stOff + mt * (16 * GST));
            ldm4(al, aoff + stOff + 6144 + mt * (16 * GST));
#pragma unroll
            for (int nt = 0; nt < 8; nt++) {
                const uint32_t* bhf = &bh[nt >> 1][(nt & 1) * 2];
                const uint32_t* blf = &bl[nt >> 1][(nt & 1) * 2];
                mma16816(acc[mt][nt], ah, bhf);
                mma16816(acc[mt][nt], ah, blf);
                mma16816(acc[mt][nt], al, bhf);
            }
        }
        __syncthreads();   // protect stage c before it is refilled at c+2
    }

    const int gRow = lane >> 2;
    const int gCol = (lane & 3) * 2;
#pragma unroll
    for (int mt = 0; mt < 2; mt++) {
#pragma unroll
        for (int half = 0; half < 2; half++) {
            const int row_g = mBase + warpM * 32 + mt * 16 + gRow + half * 8;
#pragma unroll
            for (int nt = 0; nt < 8; nt++) {
                const float v1 = acc[mt][nt][half * 2];
                const float v2 = acc[mt][nt][half * 2 + 1];
                const int col_g = nBase + warpN * 64 + nt * 8 + gCol;
                if (EPI == 0) {
                    const int b = row_g >> 11, t = row_g & 2047;
                    const int s_idx = nBase / 768;
                    const int rem = col_g - s_idx * 768;
                    const int h = rem >> 6, d = rem & 63;
                    const size_t off = ((size_t)(b * HH + h) * TT + t) * DD + d;
                    uint32_t hi, lo;
                    if (s_idx < 2) {
                        const float sc = (s_idx == 0) ? 0.125f : 1.0f;
                        const float sn = rsin[t * 32 + (d >> 1)];
                        const float cs = rcos[t * 32 + (d >> 1)];
                        split2((v1 * cs - v2 * sn) * sc,
                               (v1 * sn + v2 * cs) * sc, hi, lo);
                        __nv_bfloat16* dh = (s_idx == 0) ? g_qh : g_kh;
                        __nv_bfloat16* dl = (s_idx == 0) ? g_ql : g_kl;
                        *(uint32_t*)(dh + off) = hi;
                        *(uint32_t*)(dl + off) = lo;
                    } else {
                        split2(v1, v2, hi, lo);
                        *(uint32_t*)(g_vh + off) = hi;
                        *(uint32_t*)(g_vl + off) = lo;
                    }
                } else {
                    *(float2*)(outp + (size_t)row_g * 768 + col_g) =
                        make_float2(v1, v2);
                }
            }
        }
    }
}

// ===========================================================================
// Flash attention, split-bf16 HMMA, pre-split operands (unchanged, round-8).
// ===========================================================================
#define KST 144

__global__ __launch_bounds__(256) void attn_mma_kernel()
{
    __shared__ __align__(16) char smem[36864];
    const uint32_t sb = smem_u32(smem);
    const uint32_t sKhi = sb, sKlo = sb + 9216;
    const uint32_t sVhi = sb + 18432, sVlo = sb + 27648;

    const int tid = threadIdx.x, lane = tid & 31, warp = tid >> 5;
    const int qi = gridDim.x - 1 - blockIdx.x;
    const int bh = blockIdx.y;
    const size_t bhOff = (size_t)bh * TT * DD;
    const int qBase = qi * 128;

    {
        const int row = tid >> 1, half = tid & 1;
        const uint4* ph = (const uint4*)(g_qh + bhOff + (size_t)(qBase + row) * 64 + half * 32);
        const uint4* pl = (const uint4*)(g_ql + bhOff + (size_t)(qBase + row) * 64 + half * 32);
        const uint32_t dh = sb + (uint32_t)row * KST + half * 64;
#pragma unroll
        for (int g = 0; g < 4; g++) {
            uint4 h = ph[g], l = pl[g];
            STS4(dh + g * 16, h.x, h.y, h.z, h.w);
            STS4(dh + 18432 + g * 16, l.x, l.y, l.z, l.w);
        }
    }
    __syncthreads();

    uint32_t qh[4][4], ql[4][4];
    {
        const uint32_t aoff = sb +
            (uint32_t)(warp * 16 + (lane & 7) + ((lane >> 3) & 1) * 8) * KST +
            ((lane >> 4) & 1) * 16;
#pragma unroll
        for (int kh = 0; kh < 4; kh++) {
            ldm4(qh[kh], aoff + kh * 32);
            ldm4(ql[kh], aoff + 18432 + kh * 32);
        }
    }
    __syncthreads();

    float o[8][4];
#pragma unroll
    for (int dn = 0; dn < 8; dn++)
#pragma unroll
        for (int r = 0; r < 4; r++) o[dn][r] = 0.0f;
    float mrow[2] = {-1e30f, -1e30f};
    float lrow[2] = {0.0f, 0.0f};

    const uint32_t boff =
        (uint32_t)((lane & 7) + ((lane >> 4) & 1) * 8) * KST +
        ((lane >> 3) & 1) * 16;
    const uint32_t voff =
        (uint32_t)((lane & 7) + ((lane >> 3) & 1) * 8) * KST +
        ((lane >> 4) & 1) * 16;
    const int jtEnd = 2 * qi + 1;

    for (int jt = 0; jt <= jtEnd; jt++) {
        {
            const size_t src0 = bhOff + (size_t)jt * 64 * 64;
#pragma unroll
            for (int g = 0; g < 2; g++) {
                const int id = tid + g * 256;
                const int row = id >> 3, part = id & 7;
                const size_t s = src0 + (size_t)row * 64 + part * 8;
                const uint32_t d = (uint32_t)row * KST + part * 16;
                uint4 v;
                v = *(const uint4*)(g_kh + s); STS4(sKhi + d, v.x, v.y, v.z, v.w);
                v = *(const uint4*)(g_kl + s); STS4(sKlo + d, v.x, v.y, v.z, v.w);
                v = *(const uint4*)(g_vh + s); STS4(sVhi + d, v.x, v.y, v.z, v.w);
                v = *(const uint4*)(g_vl + s); STS4(sVlo + d, v.x, v.y, v.z, v.w);
            }
        }
        __syncthreads();

        float s[8][4];
#pragma unroll
        for (int nt = 0; nt < 8; nt++)
#pragma unroll
            for (int r = 0; r < 4; r++) s[nt][r] = 0.0f;
#pragma unroll
        for (int kh = 0; kh < 4; kh++) {
#pragma unroll
            for (int p = 0; p < 4; p++) {
                uint32_t kbh[4], kbl[4];
                ldm4(kbh, sKhi + boff + p * (16 * KST) + kh * 32);
                ldm4(kbl, sKlo + boff + p * (16 * KST) + kh * 32);
#pragma unroll
                for (int sub = 0; sub < 2; sub++) {
                    float* d = s[2 * p + sub];
                    mma16816(d, qh[kh], &kbh[sub * 2]);
                    mma16816(d, qh[kh], &kbl[sub * 2]);
                    mma16816(d, ql[kh], &kbh[sub * 2]);
                }
            }
        }

        if (jt >= 2 * qi) {
            const int row0 = qBase + warp * 16 + (lane >> 2);
            const int colb = jt * 64 + 2 * (lane & 3);
#pragma unroll
            for (int nt = 0; nt < 8; nt++) {
                const int c = colb + nt * 8;
#pragma unroll
                for (int r = 0; r < 4; r++) {
                    const int row = row0 + ((r >> 1) << 3);
                    const int col = c + (r & 1);
                    if (col > row) s[nt][r] = -1e30f;
                }
            }
        }

        float mx0 = -1e30f, mx1 = -1e30f;
#pragma unroll
        for (int nt = 0; nt < 8; nt++) {
            mx0 = fmaxf(mx0, fmaxf(s[nt][0], s[nt][1]));
            mx1 = fmaxf(mx1, fmaxf(s[nt][2], s[nt][3]));
        }
        mx0 = fmaxf(mx0, __shfl_xor_sync(0xffffffffu, mx0, 1));
        mx0 = fmaxf(mx0, __shfl_xor_sync(0xffffffffu, mx0, 2));
        mx1 = fmaxf(mx1, __shfl_xor_sync(0xffffffffu, mx1, 1));
        mx1 = fmaxf(mx1, __shfl_xor_sync(0xffffffffu, mx1, 2));
        const float mn0 = fmaxf(mrow[0], mx0);
        const float mn1 = fmaxf(mrow[1], mx1);
        const float a0 = exp2f_fast((mrow[0] - mn0) * L2E);
        const float a1 = exp2f_fast((mrow[1] - mn1) * L2E);
        mrow[0] = mn0; mrow[1] = mn1;
        float rs0 = 0.0f, rs1 = 0.0f;
#pragma unroll
        for (int nt = 0; nt < 8; nt++) {
            s[nt][0] = exp2f_fast((s[nt][0] - mn0) * L2E);
            s[nt][1] = exp2f_fast((s[nt][1] - mn0) * L2E);
            s[nt][2] = exp2f_fast((s[nt][2] - mn1) * L2E);
            s[nt][3] = exp2f_fast((s[nt][3] - mn1) * L2E);
            rs0 += s[nt][0] + s[nt][1];
            rs1 += s[nt][2] + s[nt][3];
        }
        rs0 += __shfl_xor_sync(0xffffffffu, rs0, 1);
        rs0 += __shfl_xor_sync(0xffffffffu, rs0, 2);
        rs1 += __shfl_xor_sync(0xffffffffu, rs1, 1);
        rs1 += __shfl_xor_sync(0xffffffffu, rs1, 2);
        lrow[0] = lrow[0] * a0 + rs0;
        lrow[1] = lrow[1] * a1 + rs1;
#pragma unroll
        for (int dn = 0; dn < 8; dn++) {
            o[dn][0] *= a0; o[dn][1] *= a0;
            o[dn][2] *= a1; o[dn][3] *= a1;
        }

#pragma unroll
        for (int kh = 0; kh < 4; kh++) {
            uint32_t ph[4], pl[4];
#pragma unroll
            for (int idx = 0; idx < 4; idx++) {
                const int nt = 2 * kh + (idx >> 1);
                const int rb = (idx & 1) * 2;
                split2(s[nt][rb], s[nt][rb + 1], ph[idx], pl[idx]);
            }
#pragma unroll
            for (int p = 0; p < 4; p++) {
                uint32_t vbh[4], vbl[4];
                ldm4t(vbh, sVhi + voff + kh * (16 * KST) + p * 32);
                ldm4t(vbl, sVlo + voff + kh * (16 * KST) + p * 32);
#pragma unroll
                for (int sub = 0; sub < 2; sub++) {
                    float* d = o[2 * p + sub];
                    mma16816(d, ph, &vbh[sub * 2]);
                    mma16816(d, ph, &vbl[sub * 2]);
                    mma16816(d, pl, &vbh[sub * 2]);
                }
            }
        }
        __syncthreads();
    }

    const int b = bh / HH, h = bh % HH;
    const float inv0 = 1.0f / lrow[0];
    const float inv1 = 1.0f / lrow[1];
    const int row0 = qBase + warp * 16 + (lane >> 2);
    const int colb = h * 64 + 2 * (lane & 3);
#pragma unroll
    for (int dn = 0; dn < 8; dn++) {
        const int col = colb + dn * 8;
        uint32_t hi, lo;
        split2(o[dn][0] * inv0, o[dn][1] * inv0, hi, lo);
        *(uint32_t*)(g_oh + (size_t)(b * TT + row0) * CC + col) = hi;
        *(uint32_t*)(g_ol + (size_t)(b * TT + row0) * CC + col) = lo;
        split2(o[dn][2] * inv1, o[dn][3] * inv1, hi, lo);
        *(uint32_t*)(g_oh + (size_t)(b * TT + row0 + 8) * CC + col) = hi;
        *(uint32_t*)(g_ol + (size_t)(b * TT + row0 + 8) * CC + col) = lo;
    }
}

// ---------------------------------------------------------------------------
extern "C" void kernel_launch(void* const* d_in, const int* in_sizes, int n_in,
                              void* d_out, int out_size)
{
    const float* x      = (const float*)d_in[0];
    const float* w_qkv  = (const float*)d_in[1];
    const float* w_proj = (const float*)d_in[2];
    const float* rsin   = (const float*)d_in[3];
    const float* rcos   = (const float*)d_in[4];
    float* out = (float*)d_out;

    __nv_bfloat16 *xh, *xl, *wqh, *wql, *wph, *wpl;
    cudaGetSymbolAddress((void**)&xh,  g_xh);
    cudaGetSymbolAddress((void**)&xl,  g_xl);
    cudaGetSymbolAddress((void**)&wqh, g_wqh);
    cudaGetSymbolAddress((void**)&wql, g_wql);
    cudaGetSymbolAddress((void**)&wph, g_wph);
    cudaGetSymbolAddress((void**)&wpl, g_wpl);

    split_kernel<<<1024, 256>>>(x, xh, xl, (BB * TT * CC) / 4);
    split_kernel<<<512, 256>>>(w_qkv, wqh, wql, (3 * CC * CC) / 4);
    split_kernel<<<256, 256>>>(w_proj, wph, wpl, (CC * CC) / 4);

    // QKV: M=8192 (64 x 128), N=2304 (18 x 128)
    gemm_mma_kernel<0><<<dim3(18, 64), 256>>>(rsin, rcos, nullptr);
    // Attention: 16 q-tiles of 128 x 48 (b,h)
    attn_mma_kernel<<<dim3(16, 48), 256>>>();
    // Proj: M=8192, N=768 (6 x 128)
    gemm_mma_kernel<1><<<dim3(6, 64), 256>>>(rsin, rcos, out);
}

// round 11
// speedup vs baseline: 1.1025x; 1.0207x over previous
#include <cuda_runtime.h>
#include <cuda_bf16.h>
#include <cstdint>

// Problem constants
#define BB 4
#define TT 2048
#define CC 768
#define HH 12
#define DD 64
#define NQ (BB * HH * TT * DD)

// Pre-split bf16 hi/lo tensors
__device__ __nv_bfloat16 g_qh[NQ], g_ql[NQ];
__device__ __nv_bfloat16 g_kh[NQ], g_kl[NQ];
__device__ __nv_bfloat16 g_vh[NQ], g_vl[NQ];
__device__ __nv_bfloat16 g_oh[BB * TT * CC], g_ol[BB * TT * CC];
__device__ __nv_bfloat16 g_xh[BB * TT * CC], g_xl[BB * TT * CC];
__device__ __nv_bfloat16 g_wqh[3 * CC * CC], g_wql[3 * CC * CC];
__device__ __nv_bfloat16 g_wph[CC * CC], g_wpl[CC * CC];

static __device__ __forceinline__ uint32_t smem_u32(const void* p) {
    uint32_t a;
    asm("{ .reg .u64 t; cvta.to.shared.u64 t, %1; cvt.u32.u64 %0, t; }"
        : "=r"(a) : "l"(p));
    return a;
}

static __device__ __forceinline__ void ldm4(uint32_t* r, uint32_t addr) {
    asm volatile("ldmatrix.sync.aligned.m8n8.x4.shared.b16 {%0,%1,%2,%3}, [%4];"
                 : "=r"(r[0]), "=r"(r[1]), "=r"(r[2]), "=r"(r[3]) : "r"(addr));
}
static __device__ __forceinline__ void ldm4t(uint32_t* r, uint32_t addr) {
    asm volatile("ldmatrix.sync.aligned.m8n8.x4.trans.shared.b16 {%0,%1,%2,%3}, [%4];"
                 : "=r"(r[0]), "=r"(r[1]), "=r"(r[2]), "=r"(r[3]) : "r"(addr));
}

static __device__ __forceinline__ void mma16816(float* d, const uint32_t* a,
                                                const uint32_t* b) {
    asm volatile(
        "mma.sync.aligned.m16n8k16.row.col.f32.bf16.bf16.f32 "
        "{%0,%1,%2,%3}, {%4,%5,%6,%7}, {%8,%9}, {%0,%1,%2,%3};"
        : "+f"(d[0]), "+f"(d[1]), "+f"(d[2]), "+f"(d[3])
        : "r"(a[0]), "r"(a[1]), "r"(a[2]), "r"(a[3]), "r"(b[0]), "r"(b[1]));
}

static __device__ __forceinline__ void split2(float f0, float f1,
                                              uint32_t& hi, uint32_t& lo) {
    __nv_bfloat16 h0 = __float2bfloat16(f0);
    __nv_bfloat16 h1 = __float2bfloat16(f1);
    __nv_bfloat16 l0 = __float2bfloat16(f0 - __bfloat162float(h0));
    __nv_bfloat16 l1 = __float2bfloat16(f1 - __bfloat162float(h1));
    __nv_bfloat162 hh = __halves2bfloat162(h0, h1);
    __nv_bfloat162 ll = __halves2bfloat162(l0, l1);
    hi = *reinterpret_cast<uint32_t*>(&hh);
    lo = *reinterpret_cast<uint32_t*>(&ll);
}

// FMA-pipe exp2 (no MUFU). Valid for x <= 0; clamps at -126.
static __device__ __forceinline__ float exp2f_fast(float x) {
    x = fmaxf(x, -126.0f);
    float z = x + 12582912.0f;
    int i = __float_as_int(z) - 0x4B400000;
    float f = x - (z - 12582912.0f);
    float p = 0.00133336f;
    p = fmaf(p, f, 0.00961813f);
    p = fmaf(p, f, 0.05550411f);
    p = fmaf(p, f, 0.24022651f);
    p = fmaf(p, f, 0.69314718f);
    p = fmaf(p, f, 1.0f);
    return p * __int_as_float((i + 127) << 23);
}
#define L2E 1.4426950408889634f

#define STS4(addr, a, b, c, d) \
    asm volatile("st.shared.v4.b32 [%0], {%1,%2,%3,%4};" :: \
                 "r"(addr), "r"(a), "r"(b), "r"(c), "r"(d) : "memory")
#define CP16(dst, src) \
    asm volatile("cp.async.ca.shared.global [%0], [%1], 16;" :: \
                 "r"(dst), "l"(src) : "memory")
#define CP_COMMIT() asm volatile("cp.async.commit_group;" ::: "memory")
#define CP_WAIT1()  asm volatile("cp.async.wait_group 1;" ::: "memory")
#define CP_WAIT0()  asm volatile("cp.async.wait_group 0;" ::: "memory")

// ===========================================================================
// Split kernel: fp32 -> bf16 hi/lo (vectorized, grid-stride)
// ===========================================================================
__global__ void split_kernel(const float* __restrict__ src,
                             __nv_bfloat16* __restrict__ h,
                             __nv_bfloat16* __restrict__ l, int n4)
{
    for (int i = blockIdx.x * blockDim.x + threadIdx.x; i < n4;
         i += gridDim.x * blockDim.x) {
        float4 v = ((const float4*)src)[i];
        uint32_t h01, l01, h23, l23;
        split2(v.x, v.y, h01, l01);
        split2(v.z, v.w, h23, l23);
        ((uint2*)h)[i] = make_uint2(h01, h23);
        ((uint2*)l)[i] = make_uint2(l01, l23);
    }
}

// ===========================================================================
// GEMM v4: split-bf16 HMMA, cp.async 2-stage ping-pong, warp tile 64x64.
// CTA 128(M) x 128(N), 4 warps (2M x 2N), 128 threads, K-chunk 16.
// Smem = 2 stages x 24576B = 49152B; stage: Ah[128][48] | Al | Bh | Bl.
// Per chunk per warp: 16 ldmatrix.x4 -> 96 MMAs (6 MMA/ldm reuse).
// 2 CTAs/SM (regs capped via __launch_bounds__(128,2)).
// EPI 0: RoPE scatter -> g_{q,k,v}{h,l}. EPI 1: fp32 store to outp.
// ===========================================================================
#define GST 48
#define STAGE_B 24576
#define NCHUNK 48

template <int EPI>
__global__ __launch_bounds__(128, 2) void gemm_mma_kernel(
    const float* __restrict__ rsin, const float* __restrict__ rcos,
    float* __restrict__ outp)
{
    __shared__ __align__(16) char smem[2 * STAGE_B];
    const uint32_t sb = smem_u32(smem);

    const int tid = threadIdx.x;
    const int lane = tid & 31, warp = tid >> 5;
    const int warpM = warp & 1, warpN = warp >> 1;   // 2 x 2
    const int mBase = blockIdx.y * 128, nBase = blockIdx.x * 128;

    const __nv_bfloat16* Ah = (EPI == 0) ? g_xh : g_oh;
    const __nv_bfloat16* Al = (EPI == 0) ? g_xl : g_ol;
    const __nv_bfloat16* Bh = (EPI == 0) ? g_wqh : g_wph;
    const __nv_bfloat16* Bl = (EPI == 0) ? g_wql : g_wpl;

    // loader: thread t owns A row t and B row t (hi+lo each)
    const __nv_bfloat16* sAh = Ah + (size_t)(mBase + tid) * 768;
    const __nv_bfloat16* sAl = Al + (size_t)(mBase + tid) * 768;
    const __nv_bfloat16* sBh = Bh + (size_t)(nBase + tid) * 768;
    const __nv_bfloat16* sBl = Bl + (size_t)(nBase + tid) * 768;
    const uint32_t dAh = sb + (uint32_t)tid * GST;
    const uint32_t dAl = dAh + 6144;
    const uint32_t dBh = dAh + 12288;
    const uint32_t dBl = dAh + 18432;

    const uint32_t aoff = sb +
        (uint32_t)(warpM * 64 + (lane & 7) + ((lane >> 3) & 1) * 8) * GST +
        ((lane >> 4) & 1) * 16;
    const uint32_t boff = sb + 12288 +
        (uint32_t)(warpN * 64 + (lane & 7) + ((lane >> 4) & 1) * 8) * GST +
        ((lane >> 3) & 1) * 16;

    float acc[4][8][4];
#pragma unroll
    for (int mt = 0; mt < 4; mt++)
#pragma unroll
        for (int nt = 0; nt < 8; nt++)
#pragma unroll
            for (int r = 0; r < 4; r++) acc[mt][nt][r] = 0.0f;

    // prologue: stage 0
    CP16(dAh, sAh); CP16(dAh + 16, sAh + 8);
    CP16(dAl, sAl); CP16(dAl + 16, sAl + 8);
    CP16(dBh, sBh); CP16(dBh + 16, sBh + 8);
    CP16(dBl, sBl); CP16(dBl + 16, sBl + 8);
    CP_COMMIT();

    for (int c = 0; c < NCHUNK; c++) {
        const uint32_t stOff = (uint32_t)(c & 1) * STAGE_B;
        if (c + 1 < NCHUNK) {
            const uint32_t ns = (uint32_t)((c + 1) & 1) * STAGE_B;
            const int ko = (c + 1) * 16;
            CP16(dAh + ns, sAh + ko); CP16(dAh + ns + 16, sAh + ko + 8);
            CP16(dAl + ns, sAl + ko); CP16(dAl + ns + 16, sAl + ko + 8);
            CP16(dBh + ns, sBh + ko); CP16(dBh + ns + 16, sBh + ko + 8);
            CP16(dBl + ns, sBl + ko); CP16(dBl + ns + 16, sBl + ko + 8);
            CP_COMMIT();
            CP_WAIT1();          // stage c arrived
        } else {
            CP_WAIT0();
        }
        __syncthreads();

        uint32_t bh[4][4], bl[4][4];
#pragma unroll
        for (int p = 0; p < 4; p++) {
            ldm4(bh[p], boff + stOff + p * (16 * GST));
            ldm4(bl[p], boff + stOff + 6144 + p * (16 * GST));
        }
#pragma unroll
        for (int mt = 0; mt < 4; mt++) {
            uint32_t ah[4], al[4];
            ldm4(ah, aoff + stOff + mt * (16 * GST));
            ldm4(al, aoff + stOff + 6144 + mt * (16 * GST));
#pragma unroll
            for (int nt = 0; nt < 8; nt++) {
                const uint32_t* bhf = &bh[nt >> 1][(nt & 1) * 2];
                const uint32_t* blf = &bl[nt >> 1][(nt & 1) * 2];
                mma16816(acc[mt][nt], ah, bhf);
                mma16816(acc[mt][nt], ah, blf);
                mma16816(acc[mt][nt], al, bhf);
            }
        }
        __syncthreads();   // protect stage c before refill at c+2
    }

    const int gRow = lane >> 2;
    const int gCol = (lane & 3) * 2;
#pragma unroll
    for (int mt = 0; mt < 4; mt++) {
#pragma unroll
        for (int half = 0; half < 2; half++) {
            const int row_g = mBase + warpM * 64 + mt * 16 + gRow + half * 8;
#pragma unroll
            for (int nt = 0; nt < 8; nt++) {
                const float v1 = acc[mt][nt][half * 2];
                const float v2 = acc[mt][nt][half * 2 + 1];
                const int col_g = nBase + warpN * 64 + nt * 8 + gCol;
                if (EPI == 0) {
                    const int b = row_g >> 11, t = row_g & 2047;
                    const int s_idx = nBase / 768;
                    const int rem = col_g - s_idx * 768;
                    const int h = rem >> 6, d = rem & 63;
                    const size_t off = ((size_t)(b * HH + h) * TT + t) * DD + d;
                    uint32_t hi, lo;
                    if (s_idx < 2) {
                        const float sc = (s_idx == 0) ? 0.125f : 1.0f;
                        const float sn = rsin[t * 32 + (d >> 1)];
                        const float cs = rcos[t * 32 + (d >> 1)];
                        split2((v1 * cs - v2 * sn) * sc,
                               (v1 * sn + v2 * cs) * sc, hi, lo);
                        __nv_bfloat16* dh = (s_idx == 0) ? g_qh : g_kh;
                        __nv_bfloat16* dl = (s_idx == 0) ? g_ql : g_kl;
                        *(uint32_t*)(dh + off) = hi;
                        *(uint32_t*)(dl + off) = lo;
                    } else {
                        split2(v1, v2, hi, lo);
                        *(uint32_t*)(g_vh + off) = hi;
                        *(uint32_t*)(g_vl + off) = lo;
                    }
                } else {
                    *(float2*)(outp + (size_t)row_g * 768 + col_g) =
                        make_float2(v1, v2);
                }
            }
        }
    }
}

// ===========================================================================
// Flash attention, split-bf16 HMMA, pre-split operands (unchanged, round-8).
// ===========================================================================
#define KST 144

__global__ __launch_bounds__(256) void attn_mma_kernel()
{
    __shared__ __align__(16) char smem[36864];
    const uint32_t sb = smem_u32(smem);
    const uint32_t sKhi = sb, sKlo = sb + 9216;
    const uint32_t sVhi = sb + 18432, sVlo = sb + 27648;

    const int tid = threadIdx.x, lane = tid & 31, warp = tid >> 5;
    const int qi = gridDim.x - 1 - blockIdx.x;
    const int bh = blockIdx.y;
    const size_t bhOff = (size_t)bh * TT * DD;
    const int qBase = qi * 128;

    {
        const int row = tid >> 1, half = tid & 1;
        const uint4* ph = (const uint4*)(g_qh + bhOff + (size_t)(qBase + row) * 64 + half * 32);
        const uint4* pl = (const uint4*)(g_ql + bhOff + (size_t)(qBase + row) * 64 + half * 32);
        const uint32_t dh = sb + (uint32_t)row * KST + half * 64;
#pragma unroll
        for (int g = 0; g < 4; g++) {
            uint4 h = ph[g], l = pl[g];
            STS4(dh + g * 16, h.x, h.y, h.z, h.w);
            STS4(dh + 18432 + g * 16, l.x, l.y, l.z, l.w);
        }
    }
    __syncthreads();

    uint32_t qh[4][4], ql[4][4];
    {
        const uint32_t aoff = sb +
            (uint32_t)(warp * 16 + (lane & 7) + ((lane >> 3) & 1) * 8) * KST +
            ((lane >> 4) & 1) * 16;
#pragma unroll
        for (int kh = 0; kh < 4; kh++) {
            ldm4(qh[kh], aoff + kh * 32);
            ldm4(ql[kh], aoff + 18432 + kh * 32);
        }
    }
    __syncthreads();

    float o[8][4];
#pragma unroll
    for (int dn = 0; dn < 8; dn++)
#pragma unroll
        for (int r = 0; r < 4; r++) o[dn][r] = 0.0f;
    float mrow[2] = {-1e30f, -1e30f};
    float lrow[2] = {0.0f, 0.0f};

    const uint32_t boff =
        (uint32_t)((lane & 7) + ((lane >> 4) & 1) * 8) * KST +
        ((lane >> 3) & 1) * 16;
    const uint32_t voff =
        (uint32_t)((lane & 7) + ((lane >> 3) & 1) * 8) * KST +
        ((lane >> 4) & 1) * 16;
    const int jtEnd = 2 * qi + 1;

    for (int jt = 0; jt <= jtEnd; jt++) {
        {
            const size_t src0 = bhOff + (size_t)jt * 64 * 64;
#pragma unroll
            for (int g = 0; g < 2; g++) {
                const int id = tid + g * 256;
                const int row = id >> 3, part = id & 7;
                const size_t s = src0 + (size_t)row * 64 + part * 8;
                const uint32_t d = (uint32_t)row * KST + part * 16;
                uint4 v;
                v = *(const uint4*)(g_kh + s); STS4(sKhi + d, v.x, v.y, v.z, v.w);
                v = *(const uint4*)(g_kl + s); STS4(sKlo + d, v.x, v.y, v.z, v.w);
                v = *(const uint4*)(g_vh + s); STS4(sVhi + d, v.x, v.y, v.z, v.w);
                v = *(const uint4*)(g_vl + s); STS4(sVlo + d, v.x, v.y, v.z, v.w);
            }
        }
        __syncthreads();

        float s[8][4];
#pragma unroll
        for (int nt = 0; nt < 8; nt++)
#pragma unroll
            for (int r = 0; r < 4; r++) s[nt][r] = 0.0f;
#pragma unroll
        for (int kh = 0; kh < 4; kh++) {
#pragma unroll
            for (int p = 0; p < 4; p++) {
                uint32_t kbh[4], kbl[4];
                ldm4(kbh, sKhi + boff + p * (16 * KST) + kh * 32);
                ldm4(kbl, sKlo + boff + p * (16 * KST) + kh * 32);
#pragma unroll
                for (int sub = 0; sub < 2; sub++) {
                    float* d = s[2 * p + sub];
                    mma16816(d, qh[kh], &kbh[sub * 2]);
                    mma16816(d, qh[kh], &kbl[sub * 2]);
                    mma16816(d, ql[kh], &kbh[sub * 2]);
                }
            }
        }

        if (jt >= 2 * qi) {
            const int row0 = qBase + warp * 16 + (lane >> 2);
            const int colb = jt * 64 + 2 * (lane & 3);
#pragma unroll
            for (int nt = 0; nt < 8; nt++) {
                const int c = colb + nt * 8;
#pragma unroll
                for (int r = 0; r < 4; r++) {
                    const int row = row0 + ((r >> 1) << 3);
                    const int col = c + (r & 1);
                    if (col > row) s[nt][r] = -1e30f;
                }
            }
        }

        float mx0 = -1e30f, mx1 = -1e30f;
#pragma unroll
        for (int nt = 0; nt < 8; nt++) {
            mx0 = fmaxf(mx0, fmaxf(s[nt][0], s[nt][1]));
            mx1 = fmaxf(mx1, fmaxf(s[nt][2], s[nt][3]));
        }
        mx0 = fmaxf(mx0, __shfl_xor_sync(0xffffffffu, mx0, 1));
        mx0 = fmaxf(mx0, __shfl_xor_sync(0xffffffffu, mx0, 2));
        mx1 = fmaxf(mx1, __shfl_xor_sync(0xffffffffu, mx1, 1));
        mx1 = fmaxf(mx1, __shfl_xor_sync(0xffffffffu, mx1, 2));
        const float mn0 = fmaxf(mrow[0], mx0);
        const float mn1 = fmaxf(mrow[1], mx1);
        const float a0 = exp2f_fast((mrow[0] - mn0) * L2E);
        const float a1 = exp2f_fast((mrow[1] - mn1) * L2E);
        mrow[0] = mn0; mrow[1] = mn1;
        float rs0 = 0.0f, rs1 = 0.0f;
#pragma unroll
        for (int nt = 0; nt < 8; nt++) {
            s[nt][0] = exp2f_fast((s[nt][0] - mn0) * L2E);
            s[nt][1] = exp2f_fast((s[nt][1] - mn0) * L2E);
            s[nt][2] = exp2f_fast((s[nt][2] - mn1) * L2E);
            s[nt][3] = exp2f_fast((s[nt][3] - mn1) * L2E);
            rs0 += s[nt][0] + s[nt][1];
            rs1 += s[nt][2] + s[nt][3];
        }
        rs0 += __shfl_xor_sync(0xffffffffu, rs0, 1);
        rs0 += __shfl_xor_sync(0xffffffffu, rs0, 2);
        rs1 += __shfl_xor_sync(0xffffffffu, rs1, 1);
        rs1 += __shfl_xor_sync(0xffffffffu, rs1, 2);
        lrow[0] = lrow[0] * a0 + rs0;
        lrow[1] = lrow[1] * a1 + rs1;
#pragma unroll
        for (int dn = 0; dn < 8; dn++) {
            o[dn][0] *= a0; o[dn][1] *= a0;
            o[dn][2] *= a1; o[dn][3] *= a1;
        }

#pragma unroll
        for (int kh = 0; kh < 4; kh++) {
            uint32_t ph[4], pl[4];
#pragma unroll
            for (int idx = 0; idx < 4; idx++) {
                const int nt = 2 * kh + (idx >> 1);
                const int rb = (idx & 1) * 2;
                split2(s[nt][rb], s[nt][rb + 1], ph[idx], pl[idx]);
            }
#pragma unroll
            for (int p = 0; p < 4; p++) {
                uint32_t vbh[4], vbl[4];
                ldm4t(vbh, sVhi + voff + kh * (16 * KST) + p * 32);
                ldm4t(vbl, sVlo + voff + kh * (16 * KST) + p * 32);
#pragma unroll
                for (int sub = 0; sub < 2; sub++) {
                    float* d = o[2 * p + sub];
                    mma16816(d, ph, &vbh[sub * 2]);
                    mma16816(d, ph, &vbl[sub * 2]);
                    mma16816(d, pl, &vbh[sub * 2]);
                }
            }
        }
        __syncthreads();
    }

    const int b = bh / HH, h = bh % HH;
    const float inv0 = 1.0f / lrow[0];
    const float inv1 = 1.0f / lrow[1];
    const int row0 = qBase + warp * 16 + (lane >> 2);
    const int colb = h * 64 + 2 * (lane & 3);
#pragma unroll
    for (int dn = 0; dn < 8; dn++) {
        const int col = colb + dn * 8;
        uint32_t hi, lo;
        split2(o[dn][0] * inv0, o[dn][1] * inv0, hi, lo);
        *(uint32_t*)(g_oh + (size_t)(b * TT + row0) * CC + col) = hi;
        *(uint32_t*)(g_ol + (size_t)(b * TT + row0) * CC + col) = lo;
        split2(o[dn][2] * inv1, o[dn][3] * inv1, hi, lo);
        *(uint32_t*)(g_oh + (size_t)(b * TT + row0 + 8) * CC + col) = hi;
        *(uint32_t*)(g_ol + (size_t)(b * TT + row0 + 8) * CC + col) = lo;
    }
}

// ---------------------------------------------------------------------------
extern "C" void kernel_launch(void* const* d_in, const int* in_sizes, int n_in,
                              void* d_out, int out_size)
{
    const float* x      = (const float*)d_in[0];
    const float* w_qkv  = (const float*)d_in[1];
    const float* w_proj = (const float*)d_in[2];
    const float* rsin   = (const float*)d_in[3];
    const float* rcos   = (const float*)d_in[4];
    float* out = (float*)d_out;

    __nv_bfloat16 *xh, *xl, *wqh, *wql, *wph, *wpl;
    cudaGetSymbolAddress((void**)&xh,  g_xh);
    cudaGetSymbolAddress((void**)&xl,  g_xl);
    cudaGetSymbolAddress((void**)&wqh, g_wqh);
    cudaGetSymbolAddress((void**)&wql, g_wql);
    cudaGetSymbolAddress((void**)&wph, g_wph);
    cudaGetSymbolAddress((void**)&wpl, g_wpl);

    split_kernel<<<1024, 256>>>(x, xh, xl, (BB * TT * CC) / 4);
    split_kernel<<<512, 256>>>(w_qkv, wqh, wql, (3 * CC * CC) / 4);
    split_kernel<<<256, 256>>>(w_proj, wph, wpl, (CC * CC) / 4);

    // QKV: M=8192 (64 x 128), N=2304 (18 x 128)
    gemm_mma_kernel<0><<<dim3(18, 64), 128>>>(rsin, rcos, nullptr);
    // Attention: 16 q-tiles of 128 x 48 (b,h)
    attn_mma_kernel<<<dim3(16, 48), 256>>>();
    // Proj: M=8192, N=768 (6 x 128)
    gemm_mma_kernel<1><<<dim3(6, 64), 128>>>(rsin, rcos, out);
}